// round 13
// baseline (speedup 1.0000x reference)
#include <cuda_runtime.h>

#define NT 512
#define CC 66
#define TT 100
#define JJ 22
#define HH 8
#define HD 64

// persist
#define OFF_SP    0        // sp   [66][100]  6600
#define OFF_TPT   6600     // tpT  [100][68]  6800
#define OFF_COMB  13400    // comb [100][68]  6800
#define OFF_ASM   20200    // A    [22][22]   488
// slot pool (A,D small 4352; B,C,E 6400; F 6800)
#define OFF_A     20688
#define OFF_B     25040
#define OFF_C     31440
#define OFF_D     37840
#define OFF_E     42192
#define OFF_F     48592
#define SMEM_FLOATS 55392

__device__ __forceinline__ unsigned long long pk2(float lo, float hi) {
    unsigned long long r;
    asm("mov.b64 %0, {%1, %2};" : "=l"(r) : "f"(lo), "f"(hi));
    return r;
}
__device__ __forceinline__ void upk2(float& lo, float& hi, unsigned long long v) {
    asm("mov.b64 {%0, %1}, %2;" : "=f"(lo), "=f"(hi) : "l"(v));
}
__device__ __forceinline__ void fma2(unsigned long long& acc, unsigned long long a,
                                     unsigned long long b) {
    asm("fma.rn.f32x2 %0, %1, %2, %0;" : "+l"(acc) : "l"(a), "l"(b));
}

// C[m][n] (+)= scale * sum_k A[k][m]*B[k][n] (+ biasM[m] + biasN[n])
// 8x4 register tile, f32x2 FMA, n-major lane map (proven best). Rows >= Mlim clamped.
__device__ __forceinline__ void gemm84(
    const float* __restrict__ A, const int lda,
    const float* __restrict__ B, const int ldb,
    float* __restrict__ C, const int ldc,
    const int Nt, const int K, const int Mlim,
    const float* __restrict__ biasM, const float* __restrict__ biasN,
    const float scale, const bool accum, const int t)
{
    const int mt = t / Nt;
    const int m0 = mt << 3;
    const int n0 = (t - mt * Nt) << 2;

    unsigned long long acc[4][4];
    #pragma unroll
    for (int i = 0; i < 4; i++)
        #pragma unroll
        for (int j = 0; j < 4; j++) acc[i][j] = 0ull;

    const float* Ap = A + m0;
    const float* Bp = B + n0;
    #pragma unroll 2
    for (int k = 0; k < K; ++k) {
        const float4 a0 = *(const float4*)Ap;
        const float4 a1 = *(const float4*)(Ap + 4);
        const float4 bv = *(const float4*)Bp;
        Ap += lda; Bp += ldb;
        const unsigned long long ap0 = pk2(a0.x, a0.y);
        const unsigned long long ap1 = pk2(a0.z, a0.w);
        const unsigned long long ap2 = pk2(a1.x, a1.y);
        const unsigned long long ap3 = pk2(a1.z, a1.w);
        const unsigned long long b0 = pk2(bv.x, bv.x);
        const unsigned long long b1 = pk2(bv.y, bv.y);
        const unsigned long long b2 = pk2(bv.z, bv.z);
        const unsigned long long b3 = pk2(bv.w, bv.w);
        fma2(acc[0][0], ap0, b0); fma2(acc[1][0], ap1, b0);
        fma2(acc[2][0], ap2, b0); fma2(acc[3][0], ap3, b0);
        fma2(acc[0][1], ap0, b1); fma2(acc[1][1], ap1, b1);
        fma2(acc[2][1], ap2, b1); fma2(acc[3][1], ap3, b1);
        fma2(acc[0][2], ap0, b2); fma2(acc[1][2], ap1, b2);
        fma2(acc[2][2], ap2, b2); fma2(acc[3][2], ap3, b2);
        fma2(acc[0][3], ap0, b3); fma2(acc[1][3], ap1, b3);
        fma2(acc[2][3], ap2, b3); fma2(acc[3][3], ap3, b3);
    }

    float bn[4] = {0.f, 0.f, 0.f, 0.f};
    if (biasN) { bn[0] = biasN[n0]; bn[1] = biasN[n0+1]; bn[2] = biasN[n0+2]; bn[3] = biasN[n0+3]; }
    #pragma unroll
    for (int i2 = 0; i2 < 4; i2++) {
        const int mA = m0 + (i2 << 1);
        if (mA < Mlim) {
            float lo[4], hi[4];
            #pragma unroll
            for (int j = 0; j < 4; j++) upk2(lo[j], hi[j], acc[i2][j]);
            float bmA = 0.f, bmB = 0.f;
            if (biasM) { bmA = biasM[mA]; bmB = biasM[mA + 1]; }
            float4 rA, rB;
            rA.x = fmaf(lo[0], scale, bmA + bn[0]);
            rA.y = fmaf(lo[1], scale, bmA + bn[1]);
            rA.z = fmaf(lo[2], scale, bmA + bn[2]);
            rA.w = fmaf(lo[3], scale, bmA + bn[3]);
            rB.x = fmaf(hi[0], scale, bmB + bn[0]);
            rB.y = fmaf(hi[1], scale, bmB + bn[1]);
            rB.z = fmaf(hi[2], scale, bmB + bn[2]);
            rB.w = fmaf(hi[3], scale, bmB + bn[3]);
            float* cA = C + mA * ldc + n0;
            float* cB = cA + ldc;
            if (accum) {
                const float4 oA = *(const float4*)cA;
                rA.x += oA.x; rA.y += oA.y; rA.z += oA.z; rA.w += oA.w;
            }
            *(float4*)cA = rA;
            if (mA + 1 < Mlim) {
                if (accum) {
                    const float4 oB = *(const float4*)cB;
                    rB.x += oB.x; rB.y += oB.y; rB.z += oB.z; rB.w += oB.w;
                }
                *(float4*)cB = rB;
            }
        }
    }
}

// barrier-free lane-local softmax: thread q owns column q of M[r][q], r<R.
__device__ __forceinline__ void fsm(float* __restrict__ M, const int ld,
                                    const int R, const int Qn, const int q)
{
    if (q < Qn) {
        float mx = -1e30f;
        #pragma unroll 4
        for (int r = 0; r < R; r++) mx = fmaxf(mx, M[r * ld + q]);
        float s = 0.f;
        #pragma unroll 4
        for (int r = 0; r < R; r++) {
            const float e = __expf(M[r * ld + q] - mx);
            M[r * ld + q] = e; s += e;
        }
        const float inv = 1.f / s;
        #pragma unroll 4
        for (int r = 0; r < R; r++) M[r * ld + q] *= inv;
    }
}

// stage [rows][64] head-slice of a [rows][512] weight matrix
__device__ __forceinline__ void stage_w(float* __restrict__ dst, const float* __restrict__ src,
                                        const int rows, const int ho, int i, const int n)
{
    const int total = rows << 6;
    for (; i < total; i += n)
        dst[i] = src[(i >> 6) * 512 + ho + (i & 63)];
}
// st_wo slice [64][66] -> dst[64][68], zero pad cols
__device__ __forceinline__ void stage_wo66(float* __restrict__ dst, const float* __restrict__ src,
                                           const int ho, int i, const int n)
{
    for (; i < 64 * 68; i += n) {
        const int d = i / 68, c = i - d * 68;
        dst[i] = (c < CC) ? src[(ho + d) * CC + c] : 0.f;
    }
}

__global__ __launch_bounds__(NT, 1)
void fused_kernel(
    const float* __restrict__ x,
    const float* __restrict__ adj_mask,
    const float* __restrict__ s_adj,
    const float* __restrict__ traj_mask,
    const float* __restrict__ t_adj,
    const float* __restrict__ st_wq, const float* __restrict__ st_bq,
    const float* __restrict__ st_wk, const float* __restrict__ st_bk,
    const float* __restrict__ st_wv, const float* __restrict__ st_bv,
    const float* __restrict__ st_wo, const float* __restrict__ st_bo,
    const float* __restrict__ ts_wq, const float* __restrict__ ts_bq,
    const float* __restrict__ ts_wk, const float* __restrict__ ts_bk,
    const float* __restrict__ ts_wv, const float* __restrict__ ts_bv,
    const float* __restrict__ ts_wo, const float* __restrict__ ts_bo,
    const float* __restrict__ ln_alpha, const float* __restrict__ ln_beta,
    const float* __restrict__ fc_w, const float* __restrict__ fc_b,
    float* __restrict__ out)
{
    extern __shared__ float S[];
    float* SP   = S + OFF_SP;
    float* TPT  = S + OFF_TPT;
    float* COMB = S + OFF_COMB;
    // rotating slot pointers: A,D hold <=4352; B,C,E hold <=6400; F 6800 fixed
    float* BA = S + OFF_A;
    float* BB = S + OFF_B;
    float* BC = S + OFF_C;
    float* BD = S + OFF_D;
    float* BE = S + OFF_E;
    float* BF = S + OFF_F;

    const int b   = blockIdx.x;
    const int tid = threadIdx.x;
    const float* xb = x + (size_t)b * (CC * TT);

    // ================= phase 1 =================
    {
        float* ASM = S + OFF_ASM;
        float* xs  = BA;            // [66][100] scratch (spans pool)
        float* Ms  = BA + 6600;     // [100][100]
        for (int i = tid; i < CC * TT; i += NT) xs[i] = xb[i];
        for (int i = tid; i < TT * TT; i += NT) Ms[i] = t_adj[i] * traj_mask[i];
        for (int i = tid; i < JJ * JJ; i += NT) {
            const int v = i / JJ, j = i % JJ;
            float dv = 0.f, dj = 0.f;
            for (int k = 0; k < JJ; k++) { dv += adj_mask[v * JJ + k]; dj += adj_mask[j * JJ + k]; }
            const float iv = dv > 0.f ? rsqrtf(dv) : 0.f;
            const float ij = dj > 0.f ? rsqrtf(dj) : 0.f;
            ASM[i] = s_adj[i] * adj_mask[i] * iv * ij;
        }
        __syncthreads();
        for (int i = tid; i < CC * TT; i += NT) {
            const int c = i / TT, t = i % TT;
            const int v = c / 3, dd = c % 3;
            float acc = 0.f;
            #pragma unroll
            for (int j = 0; j < JJ; j++)
                acc = fmaf(ASM[v * JJ + j], xs[(j * 3 + dd) * TT + t], acc);
            SP[i] = acc;
        }
        for (int i = tid; i < TT * 68; i += NT) {
            const int f = i / 68, c = i % 68;
            if (c >= CC) { TPT[i] = 0.f; continue; }
            const float4* mr = (const float4*)(Ms + f * TT);
            const float4* xr = (const float4*)(xs + c * TT);
            unsigned long long a01 = 0ull, a23 = 0ull;
            #pragma unroll 5
            for (int k = 0; k < TT / 4; k++) {
                const float4 m4 = mr[k], x4 = xr[k];
                fma2(a01, pk2(m4.x, m4.y), pk2(x4.x, x4.y));
                fma2(a23, pk2(m4.z, m4.w), pk2(x4.z, x4.w));
            }
            float l0, h0, l1, h1;
            upk2(l0, h0, a01); upk2(l1, h1, a23);
            TPT[i] = (l0 + h0) + (l1 + h1);
        }
        for (int i = tid; i < TT * 68; i += NT) {
            const int t = i / 68, c = i % 68;
            COMB[i] = (c < CC) ? (st_bo[c] + ts_bo[t]) : 0.f;
        }
        __syncthreads();
        // pre-stage head0: wq_st -> A, wk_st -> B, wv_st -> C
        stage_w(BA, st_wq, CC, 0, tid, NT);
        stage_w(BB, st_wk, TT, 0, tid, NT);
        stage_w(BC, st_wv, TT, 0, tid, NT);
        __syncthreads();
    }

    for (int h = 0; h < HH; h++) {
        const int ho  = h << 6;
        const int ho2 = ((h + 1) & 7) << 6;

        // M1: Q_st = A(wq)xSP -> E [64][100] | K_st = B(wk)xTPT -> D [64][68]
        if (tid < 200)       gemm84(BA, 64, SP, 100, BE, 100, 25, CC, 64, st_bq + ho, nullptr, 1.f, false, tid);
        else if (tid >= 224 && tid < 360)
                             gemm84(BB, 64, TPT, 68, BD, 68, 17, TT, 64, st_bk + ho, nullptr, 1.f, false, tid - 224);
        __syncthreads();
        // M2: S_st = D(K)xE(Q) -> F [66][100] | V_st = TPTxC(wv) -> A [66][64] | stage wo_st -> B
        if (tid < 225)       gemm84(BD, 68, BE, 100, BF, 100, 25, HD, 66, nullptr, nullptr, 0.125f, false, tid);
        else if (tid >= 256 && tid < 400)
                             gemm84(TPT, 68, BC, 64, BA, 64, 16, TT, 66, nullptr, st_bv + ho, 1.f, false, tid - 256);
        else if (tid >= 416) stage_wo66(BB, st_wo, ho, tid - 416, 96);
        __syncthreads();
        // M3: fsm_st(F; 66 rows, 100 cols) | stage wq_ts -> C (6400), wk_ts -> D (4224)
        if (tid < 128)       fsm(BF, 100, CC, TT, tid);
        else {
            for (int i = tid - 128; i < 6400 + 4224; i += 384) {
                if (i < 6400) BC[i] = ts_wq[(i >> 6) * 512 + ho + (i & 63)];
                else { const int j = i - 6400; BD[j] = ts_wk[(j >> 6) * 512 + ho + (j & 63)]; }
            }
        }
        __syncthreads();
        // M4: O_st = A(V)xF(P) -> E [64][100]
        if (tid < 200)       gemm84(BA, 64, BF, 100, BE, 100, 25, CC, 64, nullptr, nullptr, 1.f, false, tid);
        __syncthreads();
        // M5: COMB += E(O)^T x B(wo) | Q_ts = C(wq_ts)xTPT -> A [64][68] | stage wv_ts -> F
        if (tid < 221)       gemm84(BE, 100, BB, 68, COMB, 68, 17, HD, 100, nullptr, nullptr, 1.f, true, tid);
        else if (tid >= 224 && tid < 360)
                             gemm84(BC, 64, TPT, 68, BA, 68, 17, TT, 64, ts_bq + ho, nullptr, 1.f, false, tid - 224);
        else if (tid >= 384) stage_w(BF, ts_wv, CC, ho, tid - 384, 128);
        __syncthreads();
        // M6: K_ts = D(wk_ts)xSP -> C [64][100] | V_ts = SPxF(wv_ts) -> E [100][64] | stage wo_ts(part1) -> B
        if (tid < 200)       gemm84(BD, 64, SP, 100, BC, 100, 25, CC, 64, ts_bk + ho, nullptr, 1.f, false, tid);
        else if (tid >= 224 && tid < 432)
                             gemm84(SP, 100, BF, 64, BE, 64, 16, CC, 100, nullptr, ts_bv + ho, 1.f, false, tid - 224);
        else if (tid >= 448) {
            for (int i = tid - 448; i < 3200; i += 64) BB[i] = ts_wo[ho * TT + i];
        }
        __syncthreads();
        // M7: S_ts = C(Kts)xA(Qts) -> F [100][68] | stage wo_ts(part2) -> B, wq_st' -> D
        if (tid < 221)       gemm84(BC, 100, BA, 68, BF, 68, 17, HD, 100, nullptr, nullptr, 0.125f, false, tid);
        else if (tid >= 224) {
            for (int i = tid - 224; i < 3200 + 4224; i += 288) {
                if (i < 3200) BB[3200 + i] = ts_wo[ho * TT + 3200 + i];
                else { const int j = i - 3200; BD[j] = st_wq[(j >> 6) * 512 + ho2 + (j & 63)]; }
            }
        }
        __syncthreads();
        // M8: fsm_ts(F; 100 rows, 66 cols) | stage wk_st' -> C
        if (tid < 96)        fsm(BF, 68, TT, CC, tid);
        else if (tid >= 128) stage_w(BC, st_wk, TT, ho2, tid - 128, 384);
        __syncthreads();
        // M9: O_ts = E(Vts)xF(P) -> A [64][68]
        if (tid < 136)       gemm84(BE, 64, BF, 68, BA, 68, 17, TT, 64, nullptr, nullptr, 1.f, false, tid);
        __syncthreads();
        // M10: COMB += B(wo_ts)^T x A(Ots) | stage wv_st' -> E
        if (tid < 221)       gemm84(BB, 100, BA, 68, COMB, 68, 17, HD, 100, nullptr, nullptr, 1.f, true, tid);
        else if (tid >= 224) stage_w(BE, st_wv, TT, ho2, tid - 224, 288);
        __syncthreads();

        // rotate slots: newA=D, newD=A; newB=C, newC=E, newE=B  (F fixed)
        { float* t = BA; BA = BD; BD = t; t = BB; BB = BC; BC = BE; BE = t; }
    }

    // ================= phase 3 =================
    {
        float* fw = S + OFF_A;     // [100][100] spans pool start
        for (int i = tid; i < TT * TT; i += NT) fw[i] = fc_w[i];
        if (tid < TT) {
            const int t = tid;
            float mean = 0.f;
            for (int c = 0; c < CC; c++) mean += COMB[t * 68 + c];
            mean *= (1.f / 66.f);
            float var = 0.f;
            for (int c = 0; c < CC; c++) {
                const float v = COMB[t * 68 + c] - mean;
                var = fmaf(v, v, var);
            }
            var *= (1.f / 66.f);
            const float inv = rsqrtf(var + 1e-5f);
            for (int c = 0; c < CC; c++) {
                const float y = (COMB[t * 68 + c] - mean) * inv * ln_alpha[c] + ln_beta[c];
                SP[c * TT + t] = y + xb[c * TT + t];
            }
        }
        __syncthreads();
        float* outb = out + (size_t)b * (CC * TT);
        for (int i = tid; i < CC * TT; i += NT) {
            const int c = i / TT, f = i % TT;
            const float4* zr = (const float4*)(SP + c * TT);
            const float4* fr = (const float4*)(fw + f * TT);
            unsigned long long a01 = 0ull, a23 = 0ull;
            #pragma unroll 5
            for (int k = 0; k < TT / 4; k++) {
                const float4 z4 = zr[k], f4 = fr[k];
                fma2(a01, pk2(z4.x, z4.y), pk2(f4.x, f4.y));
                fma2(a23, pk2(z4.z, z4.w), pk2(f4.z, f4.w));
            }
            float l0, h0, l1, h1;
            upk2(l0, h0, a01); upk2(l1, h1, a23);
            outb[i] = tanhf(fc_b[f] + (l0 + h0) + (l1 + h1));
        }
    }
}

extern "C" void kernel_launch(void* const* d_in, const int* in_sizes, int n_in,
                              void* d_out, int out_size) {
    const float* x         = (const float*)d_in[0];
    const float* adj_mask  = (const float*)d_in[1];
    const float* s_adj     = (const float*)d_in[2];
    const float* traj_mask = (const float*)d_in[3];
    const float* t_adj     = (const float*)d_in[4];
    const float* st_wq = (const float*)d_in[5];  const float* st_bq = (const float*)d_in[6];
    const float* st_wk = (const float*)d_in[7];  const float* st_bk = (const float*)d_in[8];
    const float* st_wv = (const float*)d_in[9];  const float* st_bv = (const float*)d_in[10];
    const float* st_wo = (const float*)d_in[11]; const float* st_bo = (const float*)d_in[12];
    const float* ts_wq = (const float*)d_in[13]; const float* ts_bq = (const float*)d_in[14];
    const float* ts_wk = (const float*)d_in[15]; const float* ts_bk = (const float*)d_in[16];
    const float* ts_wv = (const float*)d_in[17]; const float* ts_bv = (const float*)d_in[18];
    const float* ts_wo = (const float*)d_in[19]; const float* ts_bo = (const float*)d_in[20];
    const float* ln_alpha = (const float*)d_in[21];
    const float* ln_beta  = (const float*)d_in[22];
    const float* fc_w     = (const float*)d_in[23];
    const float* fc_b     = (const float*)d_in[24];
    float* out = (float*)d_out;

    const int B = in_sizes[0] / (CC * TT);
    const size_t smem = (size_t)SMEM_FLOATS * sizeof(float);
    cudaFuncSetAttribute(fused_kernel, cudaFuncAttributeMaxDynamicSharedMemorySize, (int)smem);

    fused_kernel<<<B, NT, smem>>>(
        x, adj_mask, s_adj, traj_mask, t_adj,
        st_wq, st_bq, st_wk, st_bk, st_wv, st_bv, st_wo, st_bo,
        ts_wq, ts_bq, ts_wk, ts_bk, ts_wv, ts_bv, ts_wo, ts_bo,
        ln_alpha, ln_beta, fc_w, fc_b, out);
}